// round 9
// baseline (speedup 1.0000x reference)
#include <cuda_runtime.h>
#include <cstdint>

// Problem constants (x = [4096, 8192, 1] f32, G = 7)
constexpr int B_ROWS = 4096;
constexpr int I_COLS = 8192;
constexpr int G      = 7;

constexpr int BT    = 512;   // threads per block, 3 CTAs/SM
constexpr int NW    = 16;    // warps
constexpr int NB    = 640;   // quantile buckets (mean ~12.8)
constexpr int NPAIR = NB / 2;
constexpr int SLOTS = 16;    // elements per lane (= per-warp slot rounds)

// ---- dynamic shared memory layout (~73.2 KB -> 3 CTAs/SM) ----
constexpr size_t OFF_DST  = 0;                    // u32 dst[8192]          32768
constexpr size_t OFF_HI   = OFF_DST + 32768;      // u16 hi[8192] / u64 id-cache[2048]  16384
constexpr size_t OFF_CNT  = OFF_HI  + 16384;      // u16 cnt[16*640] (counts -> cursors) 20480
constexpr size_t OFF_U    = OFF_CNT + 20480;      // u32 U[640]             2560
constexpr size_t OFF_BASE = OFF_U   + 2560;       // u32 base[641]          2564
constexpr size_t OFF_AUX  = OFF_BASE + 2564;      // u32 aux[16]
constexpr size_t OFF_SCAL = OFF_AUX + 64;         // f32 scal[32]
constexpr size_t SMEM_BYTES = OFF_SCAL + 128;

// key transform: ascending u32 == descending float
__device__ __forceinline__ uint32_t kd(float f) {
    uint32_t b = __float_as_uint(f);
    uint32_t m = (uint32_t)(((int32_t)b) >> 31) | 0x80000000u;
    return ~(b ^ m);
}
__device__ __forceinline__ float inv_kd(uint32_t k) {
    uint32_t u = ~k;
    return __uint_as_float((u & 0x80000000u) ? (u ^ 0x80000000u) : ~u);
}

// bucket of x: MUFU-based guess from the sigmoid fit of Phi(x), corrected by
// an exact, monotone table walk (correctness depends only on the compares).
__device__ __forceinline__ int bucket_of(float x, uint32_t u, const uint32_t* __restrict__ U) {
    float z = fmaf(0.07056f * x * x, x, 1.5976f * x);
    int b = (int)((float)NB * __frcp_rn(1.0f + __expf(z)));   // ~ NB*(1-Phi(x))
    b = max(0, min(NB - 1, b));
    while (b < NB - 1 && u >= U[b]) ++b;
    while (b > 0 && u < U[b - 1]) --b;
    return b;
}

// ---------------- warp-register bitonic sorts (ascending) ----------------
template <int R>
__device__ __forceinline__ void bitonic32(uint32_t v[R], int lane) {
    constexpr int N = R * 32;
    #pragma unroll
    for (int k = 2; k <= N; k <<= 1) {
        #pragma unroll
        for (int j = k >> 1; j > 0; j >>= 1) {
            if (j >= 32) {
                const int jr = j >> 5;
                #pragma unroll
                for (int r = 0; r < R; r++) {
                    if ((r & jr) == 0) {
                        const int r2 = r + jr;
                        const int e  = r * 32 + lane;
                        const bool up = ((e & k) == 0);
                        uint32_t a = v[r], b = v[r2];
                        uint32_t lo = min(a, b), hi = max(a, b);
                        v[r]  = up ? lo : hi;
                        v[r2] = up ? hi : lo;
                    }
                }
            } else {
                #pragma unroll
                for (int r = 0; r < R; r++) {
                    const int e = r * 32 + lane;
                    uint32_t w = __shfl_xor_sync(0xFFFFFFFFu, v[r], j);
                    const bool up = ((e & k) == 0);
                    const bool keep_lo = (((e & j) == 0) == up);
                    v[r] = keep_lo ? min(v[r], w) : max(v[r], w);
                }
            }
        }
    }
}

template <int R>
__device__ __forceinline__ void bitonic64(unsigned long long v[R], int lane) {
    constexpr int N = R * 32;
    #pragma unroll
    for (int k = 2; k <= N; k <<= 1) {
        #pragma unroll
        for (int j = k >> 1; j > 0; j >>= 1) {
            if (j >= 32) {
                const int jr = j >> 5;
                #pragma unroll
                for (int r = 0; r < R; r++) {
                    if ((r & jr) == 0) {
                        const int r2 = r + jr;
                        const int e  = r * 32 + lane;
                        const bool up = ((e & k) == 0);
                        unsigned long long a = v[r], b = v[r2];
                        unsigned long long lo = a < b ? a : b;
                        unsigned long long hi = a < b ? b : a;
                        v[r]  = up ? lo : hi;
                        v[r2] = up ? hi : lo;
                    }
                }
            } else {
                #pragma unroll
                for (int r = 0; r < R; r++) {
                    const int e = r * 32 + lane;
                    unsigned long long w = __shfl_xor_sync(0xFFFFFFFFu, v[r], j);
                    const bool up = ((e & k) == 0);
                    const bool keep_lo = (((e & j) == 0) == up);
                    v[r] = keep_lo ? (v[r] < w ? v[r] : w) : (v[r] > w ? v[r] : w);
                }
            }
        }
    }
}

// payload reconstruct for wide buckets: 45-bit key-offset|idx as u64
__device__ __forceinline__ unsigned long long ld48(
    const uint32_t* __restrict__ dst, const unsigned short* __restrict__ hi, int i) {
    return ((unsigned long long)hi[i] << 32) | (unsigned long long)dst[i];
}

__device__ __forceinline__ void emit(
    int gr, uint32_t idx, uint32_t off, uint32_t lo,
    float* __restrict__ si, float* s_top, float* s_bot)
{
    si[gr] = (float)idx;
    if (gr < G || gr >= I_COLS - G) {
        float fv = inv_kd(lo + off);
        if (gr < G) s_top[gr] = fv;
        else        s_bot[gr - (I_COLS - G)] = fv;
    }
}

// 16-wide sub-warp sort (two narrow buckets per warp)
__device__ __forceinline__ void sort16_u32(
    const uint32_t* __restrict__ dst, int start, int size, uint32_t lo,
    int m, float* __restrict__ si, float* s_top, float* s_bot)
{
    uint32_t v = (m < size) ? dst[start + m] : 0xFFFFFFFFu;
    #pragma unroll
    for (int k = 2; k <= 16; k <<= 1) {
        #pragma unroll
        for (int j = k >> 1; j > 0; j >>= 1) {
            uint32_t w = __shfl_xor_sync(0xFFFFFFFFu, v, j, 16);
            const bool up = ((m & k) == 0);
            const bool keep_lo = (((m & j) == 0) == up);
            v = keep_lo ? min(v, w) : max(v, w);
        }
    }
    if (m < size) emit(start + m, v & 8191u, v >> 13, lo, si, s_top, s_bot);
}

// narrow 32-wide path (u32 payload)
template <int R>
__device__ __forceinline__ void sort_bucket_u32(
    const uint32_t* __restrict__ dst, int start, int size, uint32_t lo,
    int lane, float* __restrict__ si, float* s_top, float* s_bot)
{
    uint32_t v[R];
    #pragma unroll
    for (int r = 0; r < R; r++) {
        int m = r * 32 + lane;
        v[r] = (m < size) ? dst[start + m] : 0xFFFFFFFFu;
    }
    bitonic32<R>(v, lane);
    #pragma unroll
    for (int r = 0; r < R; r++) {
        int m = r * 32 + lane;
        if (m < size) emit(start + m, v[r] & 8191u, v[r] >> 13, lo, si, s_top, s_bot);
    }
}

// wide path (48-bit payload reconstructed into u64)
template <int R>
__device__ __forceinline__ void sort_bucket_w(
    const uint32_t* __restrict__ dst, const unsigned short* __restrict__ hi,
    int start, int size, uint32_t lo,
    int lane, float* __restrict__ si, float* s_top, float* s_bot)
{
    unsigned long long v[R];
    #pragma unroll
    for (int r = 0; r < R; r++) {
        int m = r * 32 + lane;
        v[r] = (m < size) ? ld48(dst, hi, start + m) : ~0ull;
    }
    bitonic64<R>(v, lane);
    #pragma unroll
    for (int r = 0; r < R; r++) {
        int m = r * 32 + lane;
        if (m < size)
            emit(start + m, (uint32_t)(v[r] & 8191u), (uint32_t)(v[r] >> 13), lo,
                 si, s_top, s_bot);
    }
}

// unconditional-correctness fallback (statistically unreachable)
__device__ void bucket_fallback(
    const uint32_t* __restrict__ dst, const unsigned short* __restrict__ hi,
    int start, int size, uint32_t lo, int lane,
    float* __restrict__ si, float* s_top, float* s_bot)
{
    for (int m = lane; m < size; m += 32) {
        unsigned long long p = ld48(dst, hi, start + m);
        int rank = 0;
        for (int j = 0; j < size; j++) rank += (ld48(dst, hi, start + j) < p);
        emit(start + rank, (uint32_t)(p & 8191u), (uint32_t)(p >> 13), lo,
             si, s_top, s_bot);
    }
}

__device__ __forceinline__ void process_bucket(
    const uint32_t* __restrict__ dst, const unsigned short* __restrict__ hi,
    int start, int size, uint32_t lo, bool narrow, int lane,
    float* __restrict__ si, float* s_top, float* s_bot)
{
    if (size <= 0) return;
    if (narrow) {
        if      (size <= 32)  sort_bucket_u32<1>(dst, start, size, lo, lane, si, s_top, s_bot);
        else if (size <= 64)  sort_bucket_u32<2>(dst, start, size, lo, lane, si, s_top, s_bot);
        else if (size <= 128) sort_bucket_u32<4>(dst, start, size, lo, lane, si, s_top, s_bot);
        else                  bucket_fallback(dst, hi, start, size, lo, lane, si, s_top, s_bot);
    } else {
        if      (size <= 32)  sort_bucket_w<1>(dst, hi, start, size, lo, lane, si, s_top, s_bot);
        else if (size <= 64)  sort_bucket_w<2>(dst, hi, start, size, lo, lane, si, s_top, s_bot);
        else if (size <= 128) sort_bucket_w<4>(dst, hi, start, size, lo, lane, si, s_top, s_bot);
        else                  bucket_fallback(dst, hi, start, size, lo, lane, si, s_top, s_bot);
    }
}

extern __shared__ unsigned char smem_raw[];

__global__ void __launch_bounds__(BT, 3)
portfolio_noatomic_kernel(const float* __restrict__ x, float* __restrict__ out)
{
    uint32_t*           dst   = (uint32_t*)(smem_raw + OFF_DST);
    unsigned short*     hiarr = (unsigned short*)(smem_raw + OFF_HI);
    unsigned long long* idc   = (unsigned long long*)(smem_raw + OFF_HI);  // id-cache alias
    unsigned short*     cnt   = (unsigned short*)(smem_raw + OFF_CNT);     // counts -> cursors
    uint32_t*           U     = (uint32_t*)(smem_raw + OFF_U);
    uint32_t*           base  = (uint32_t*)(smem_raw + OFF_BASE);
    uint32_t*           aux   = (uint32_t*)(smem_raw + OFF_AUX);
    float*              s_top = (float*)(smem_raw + OFF_SCAL);             // [7]
    float*              s_bot = s_top + 8;                                 // [7]
    float*              s_win = s_top + 16;                                // [7]
    float*              s_los = s_top + 24;                                // [7]

    const int tid  = threadIdx.x;
    const int wid  = tid >> 5;
    const int lane = tid & 31;
    const unsigned lt = (1u << lane) - 1u;
    const int row  = blockIdx.x;
    const float* xr = x + (size_t)row * I_COLS;

    // ---- init: monotone splitter table + zero counts ----
    for (int i = tid; i < NB - 1; i += BT) {
        float pi = (float)(i + 1) * (1.0f / (float)NB);
        float q  = 0.58754f * __logf((1.0f - pi) / pi);
        U[i] = kd(q);
    }
    if (tid == 0) { U[NB - 1] = 0xFFFFFFFFu; base[NB] = I_COLS; }
    for (int i = tid; i < (NW * NB) / 2; i += BT) ((uint32_t*)cnt)[i] = 0;
    __syncthreads();

    // ---- Phase 1: bucket + per-warp u16 counts (match-based, NO atomics) ----
    // Element position p = wid*512 + s*32 + lane; counting order == position
    // order -> fully stable sort (ties -> index ascending).
    {
        unsigned long long idacc = 0;
        #pragma unroll
        for (int s = 0; s < SLOTS; s++) {
            int p = (wid << 9) + (s << 5) + lane;
            float xv = xr[p];                        // coalesced 128B per slot
            uint32_t u = kd(xv);
            int b = bucket_of(xv, u, U);
            idacc |= (unsigned long long)(uint32_t)b << ((s & 3) * 16);
            if ((s & 3) == 3) {
                idc[(wid << 7) + ((s >> 2) << 5) + lane] = idacc;
                idacc = 0;
            }
            unsigned mask = __match_any_sync(0xFFFFFFFFu, (unsigned)b);
            if (lane == __ffs(mask) - 1) {
                int a = wid * NB + b;                // single writer, program-ordered
                cnt[a] = (unsigned short)(cnt[a] + (unsigned)__popc(mask));
            }
        }
    }
    __syncthreads();

    // ---- Phase 2: block scan -> base[] and per-warp start cursors (in cnt) ----
    {
        int t = tid;
        uint32_t tot0 = 0, tot1 = 0;
        if (t < NPAIR) {
            int b0 = 2 * t, b1 = b0 + 1;
            #pragma unroll
            for (int w = 0; w < NW; w++) {
                tot0 += cnt[w * NB + b0];
                tot1 += cnt[w * NB + b1];
            }
        }
        uint32_t tsum = tot0 + tot1;
        uint32_t inc = tsum;
        #pragma unroll
        for (int o = 1; o < 32; o <<= 1) {
            uint32_t n = __shfl_up_sync(0xFFFFFFFFu, inc, o);
            if (lane >= o) inc += n;
        }
        if (lane == 31) aux[wid] = inc;
        __syncthreads();
        if (wid == 0) {
            uint32_t v  = (lane < NW) ? aux[lane] : 0;
            uint32_t vi = v;
            #pragma unroll
            for (int o = 1; o < 32; o <<= 1) {
                uint32_t n = __shfl_up_sync(0xFFFFFFFFu, vi, o);
                if (lane >= o) vi += n;
            }
            if (lane < NW) aux[lane] = vi - v;       // exclusive warp prefix
        }
        __syncthreads();
        if (t < NPAIR) {
            int b0 = 2 * t, b1 = b0 + 1;
            uint32_t excl = aux[wid] + (inc - tsum);
            base[b0] = excl; base[b1] = excl + tot0;
            uint32_t r0 = excl, r1 = excl + tot0;
            #pragma unroll
            for (int w = 0; w < NW; w++) {
                uint32_t c0 = cnt[w * NB + b0];
                uint32_t c1 = cnt[w * NB + b1];
                cnt[w * NB + b0] = (unsigned short)r0; r0 += c0;
                cnt[w * NB + b1] = (unsigned short)r1; r1 += c1;
            }
        }
    }
    __syncthreads();

    // ---- Phase 3: match-aggregated cursor scatter (NO atomics) ----
    {
        unsigned long long idw[4];
        #pragma unroll
        for (int r = 0; r < 4; r++) idw[r] = idc[(wid << 7) + (r << 5) + lane];
        __syncthreads();                             // ids safe before hi overwrite
        #pragma unroll
        for (int s = 0; s < SLOTS; s++) {
            int p = (wid << 9) + (s << 5) + lane;
            float xv = xr[p];                        // L1 re-hit
            uint32_t u = kd(xv);
            int b = (int)((idw[s >> 2] >> ((s & 3) * 16)) & 0xFFFFu);
            uint32_t lo = b ? U[b - 1] : 0u;
            uint32_t off = u - lo;
            unsigned mask = __match_any_sync(0xFFFFFFFFu, (unsigned)b);
            int leader = __ffs(mask) - 1;
            uint32_t cb = 0;
            if (lane == leader) {
                int a = wid * NB + b;
                cb = cnt[a];
                cnt[a] = (unsigned short)(cb + (unsigned)__popc(mask));
            }
            cb = __shfl_sync(0xFFFFFFFFu, cb, leader);
            uint32_t pos = cb + (unsigned)__popc(mask & lt);
            dst[pos]   = (off << 13) | (uint32_t)p;  // low 32 of 45-bit payload
            hiarr[pos] = (unsigned short)(off >> 19);// high bits (0 for narrow)
        }
    }
    __syncthreads();

    // ---- b_c zero fill (independent; overlaps with sorts) ----
    float* bc = out + (size_t)row * I_COLS;
    float* si = out + (size_t)B_ROWS * I_COLS + (size_t)row * I_COLS;
    {
        float4 z = make_float4(0.f, 0.f, 0.f, 0.f);
        float4* bc4 = (float4*)bc;
        #pragma unroll
        for (int q4 = 0; q4 < 4; q4++) bc4[tid + q4 * BT] = z;
    }

    // ---- Phase 4: per-warp register bitonic sorts ----
    for (int pb = wid; pb < NPAIR; pb += NW) {
        int b0 = 2 * pb, b1 = b0 + 1;
        int st0 = base[b0], st1 = base[b1], end1 = base[b1 + 1];
        int s0 = st1 - st0, s1 = end1 - st1;
        uint32_t lo0 = b0 ? U[b0 - 1] : 0u;
        uint32_t lo1 = U[b0];
        bool nar0 = (U[b0] - lo0) <= (1u << 19);
        bool nar1 = (U[b1] - lo1) <= (1u << 19);
        if (s0 <= 16 && s1 <= 16 && nar0 && nar1) {
            const int half = lane >> 4, m = lane & 15;
            sort16_u32(dst, half ? st1 : st0, half ? s1 : s0,
                       half ? lo1 : lo0, m, si, s_top, s_bot);
        } else {
            process_bucket(dst, hiarr, st0, s0, lo0, nar0, lane, si, s_top, s_bot);
            process_bucket(dst, hiarr, st1, s1, lo1, nar1, lane, si, s_top, s_bot);
        }
    }
    __syncthreads();

    // ---- softmaxes ----
    if (tid == 0) {
        float m = s_top[0];
        #pragma unroll
        for (int i = 1; i < G; i++) m = fmaxf(m, s_top[i]);
        float e[G], s = 0.0f;
        #pragma unroll
        for (int i = 0; i < G; i++) { e[i] = expf(s_top[i] - m); s += e[i]; }
        float inv = 1.0f / s;
        #pragma unroll
        for (int i = 0; i < G; i++) s_win[i] = e[i] * inv;

        float m2 = 1.0f - s_bot[0];
        #pragma unroll
        for (int i = 1; i < G; i++) m2 = fmaxf(m2, 1.0f - s_bot[i]);
        float e2[G], s2 = 0.0f;
        #pragma unroll
        for (int i = 0; i < G; i++) { e2[i] = expf((1.0f - s_bot[i]) - m2); s2 += e2[i]; }
        float inv2 = 1.0f / s2;
        #pragma unroll
        for (int i = 0; i < G; i++) s_los[i] = -e2[i] * inv2;
    }
    __syncthreads();

    if (tid < G)          bc[tid] = s_win[tid];
    else if (tid < 2 * G) bc[I_COLS - G + (tid - G)] = s_los[tid - G];
}

extern "C" void kernel_launch(void* const* d_in, const int* in_sizes, int n_in,
                              void* d_out, int out_size)
{
    (void)in_sizes; (void)n_in; (void)out_size;
    const float* x = (const float*)d_in[0];
    float* out = (float*)d_out;

    cudaFuncSetAttribute(portfolio_noatomic_kernel,
                         cudaFuncAttributeMaxDynamicSharedMemorySize,
                         (int)SMEM_BYTES);
    portfolio_noatomic_kernel<<<B_ROWS, BT, SMEM_BYTES>>>(x, out);
}

// round 10
// speedup vs baseline: 1.3090x; 1.3090x over previous
#include <cuda_runtime.h>
#include <cstdint>

// Problem constants (x = [4096, 8192, 1] f32, G = 7)
constexpr int B_ROWS = 4096;
constexpr int I_COLS = 8192;
constexpr int G      = 7;

constexpr int BT    = 512;   // threads per block, 2 CTAs/SM
constexpr int NW    = 16;    // warps
constexpr int NB    = 640;   // quantile buckets (mean ~12.8)
constexpr int NPAIR = NB / 2;
constexpr int CAP   = 28;    // slot capacity per bucket (P(overflow) ~ 3e-5)

// ---- dynamic shared memory layout (~112.3 KB -> 2 CTAs/SM) ----
constexpr size_t OFF_SLOT = 0;                                 // u32 slots[NB*CAP]  71680
constexpr size_t OFF_OVF  = OFF_SLOT + (size_t)NB * CAP * 4;   // u32 ovf[8192]      32768
constexpr size_t OFF_CNT  = OFF_OVF  + (size_t)I_COLS * 4;     // u32 cnt[NB]
constexpr size_t OFF_U    = OFF_CNT  + NB * 4;                 // u32 U[NB]
constexpr size_t OFF_BASE = OFF_U    + NB * 4;                 // u32 base[NB+1]
constexpr size_t OFF_AUX  = OFF_BASE + (NB + 1) * 4;           // u32 aux[16]
constexpr size_t OFF_OVFN = OFF_AUX  + 64;                     // u32 ovfn
constexpr size_t OFF_SCAL = OFF_OVFN + 16;                     // f32 scal[32]
constexpr size_t SMEM_BYTES = OFF_SCAL + 128;

// key transform: ascending u32 == descending float
__device__ __forceinline__ uint32_t kd(float f) {
    uint32_t b = __float_as_uint(f);
    uint32_t m = (uint32_t)(((int32_t)b) >> 31) | 0x80000000u;
    return ~(b ^ m);
}
__device__ __forceinline__ float inv_kd(uint32_t k) {
    uint32_t u = ~k;
    return __uint_as_float((u & 0x80000000u) ? (u ^ 0x80000000u) : ~u);
}

// bucket of x: MUFU-based guess from the sigmoid fit of Phi(x), corrected by
// an exact, monotone table walk (correctness depends only on the compares).
__device__ __forceinline__ int bucket_of(float x, uint32_t u, const uint32_t* __restrict__ U) {
    float z = fmaf(0.07056f * x * x, x, 1.5976f * x);
    int b = (int)((float)NB * __frcp_rn(1.0f + __expf(z)));   // ~ NB*(1-Phi(x))
    b = max(0, min(NB - 1, b));
    while (b < NB - 1 && u >= U[b]) ++b;
    while (b > 0 && u < U[b - 1]) --b;
    return b;
}

__device__ __forceinline__ void emit_packed(
    int gr, uint32_t idx, uint32_t off, uint32_t lo,
    float* __restrict__ si, float* s_top, float* s_bot)
{
    si[gr] = (float)idx;
    if (gr < G || gr >= I_COLS - G) {
        float fv = inv_kd(lo + off);
        if (gr < G) s_top[gr] = fv;
        else        s_bot[gr - (I_COLS - G)] = fv;
    }
}
__device__ __forceinline__ void emit_val(
    int gr, uint32_t idx, float val,
    float* __restrict__ si, float* s_top, float* s_bot)
{
    si[gr] = (float)idx;
    if (gr < G)           s_top[gr] = val;
    else if (gr >= I_COLS - G) s_bot[gr - (I_COLS - G)] = val;
}

// ---- 16-wide sub-warp sort: two narrow buckets per warp ----
__device__ __forceinline__ void sort16_u32(
    const uint32_t* __restrict__ sb, int size, int gbase, uint32_t lo,
    int m, float* __restrict__ si, float* s_top, float* s_bot)
{
    uint32_t v = (m < size) ? sb[m] : 0xFFFFFFFFu;
    #pragma unroll
    for (int k = 2; k <= 16; k <<= 1) {
        #pragma unroll
        for (int j = k >> 1; j > 0; j >>= 1) {
            uint32_t w = __shfl_xor_sync(0xFFFFFFFFu, v, j, 16);
            const bool up = ((m & k) == 0);
            const bool keep_lo = (((m & j) == 0) == up);
            v = keep_lo ? min(v, w) : max(v, w);
        }
    }
    if (m < size) emit_packed(gbase + m, v & 8191u, v >> 13, lo, si, s_top, s_bot);
}

// ---- 32-wide narrow bucket (size <= CAP <= 32), u32 payload ----
__device__ __forceinline__ void sort_bucket_u32(
    const uint32_t* __restrict__ sb, int size, int gbase, uint32_t lo,
    int lane, float* __restrict__ si, float* s_top, float* s_bot)
{
    uint32_t v = (lane < size) ? sb[lane] : 0xFFFFFFFFu;
    #pragma unroll
    for (int k = 2; k <= 32; k <<= 1) {
        #pragma unroll
        for (int j = k >> 1; j > 0; j >>= 1) {
            uint32_t w = __shfl_xor_sync(0xFFFFFFFFu, v, j);
            const bool up = ((lane & k) == 0);
            const bool keep_lo = (((lane & j) == 0) == up);
            v = keep_lo ? min(v, w) : max(v, w);
        }
    }
    if (lane < size) emit_packed(gbase + lane, v & 8191u, v >> 13, lo, si, s_top, s_bot);
}

// ---- wide bucket (size <= CAP): slots hold idx; rebuild 45-bit key ----
__device__ __forceinline__ void sort_bucket_wide(
    const uint32_t* __restrict__ sb, int size, int gbase,
    const float* __restrict__ xr, int lane,
    float* __restrict__ si, float* s_top, float* s_bot)
{
    unsigned long long v = ~0ull;
    if (lane < size) {
        uint32_t idx = sb[lane];
        v = ((unsigned long long)kd(xr[idx]) << 13) | idx;
    }
    #pragma unroll
    for (int k = 2; k <= 32; k <<= 1) {
        #pragma unroll
        for (int j = k >> 1; j > 0; j >>= 1) {
            unsigned long long w = __shfl_xor_sync(0xFFFFFFFFu, v, j);
            const bool up = ((lane & k) == 0);
            const bool keep_lo = (((lane & j) == 0) == up);
            v = keep_lo ? (v < w ? v : w) : (v > w ? v : w);
        }
    }
    if (lane < size)
        emit_val(gbase + lane, (uint32_t)(v & 8191u), inv_kd((uint32_t)(v >> 13)),
                 si, s_top, s_bot);
}

// ---- unconditional-correctness fallback for overflowed buckets ----
__device__ void bucket_fallback(
    const uint32_t* __restrict__ sb, int size, int gbase, int b, bool narrow,
    const uint32_t* __restrict__ ovf, int ovfTotal,
    const float* __restrict__ xr, int lane,
    float* __restrict__ si, float* s_top, float* s_bot)
{
    const int n0 = min(size, CAP);
    // rank of one element (key recomputed from gmem -> uniform & exact)
    auto rank_of = [&](unsigned long long me) -> int {
        int r = 0;
        for (int t = 0; t < n0; t++) {
            uint32_t p2 = sb[t];
            uint32_t i2 = narrow ? (p2 & 8191u) : p2;
            unsigned long long k2 = ((unsigned long long)kd(xr[i2]) << 13) | i2;
            r += (k2 < me);
        }
        for (int j = 0; j < ovfTotal; j++) {
            uint32_t o = ovf[j];
            if ((int)(o >> 13) == b) {
                uint32_t i2 = o & 8191u;
                unsigned long long k2 = ((unsigned long long)kd(xr[i2]) << 13) | i2;
                r += (k2 < me);
            }
        }
        return r;
    };
    if (lane < n0) {
        uint32_t pay = sb[lane];
        uint32_t idx = narrow ? (pay & 8191u) : pay;
        float xv = xr[idx];
        unsigned long long me = ((unsigned long long)kd(xv) << 13) | idx;
        emit_val(gbase + rank_of(me), idx, xv, si, s_top, s_bot);
    }
    for (int j = lane; j < ovfTotal; j += 32) {
        uint32_t o = ovf[j];
        if ((int)(o >> 13) == b) {
            uint32_t idx = o & 8191u;
            float xv = xr[idx];
            unsigned long long me = ((unsigned long long)kd(xv) << 13) | idx;
            emit_val(gbase + rank_of(me), idx, xv, si, s_top, s_bot);
        }
    }
}

extern __shared__ unsigned char smem_raw[];

__global__ void __launch_bounds__(BT, 2)
portfolio_slot_kernel(const float* __restrict__ x, float* __restrict__ out)
{
    uint32_t* slots = (uint32_t*)(smem_raw + OFF_SLOT);
    uint32_t* ovf   = (uint32_t*)(smem_raw + OFF_OVF);
    uint32_t* cnt   = (uint32_t*)(smem_raw + OFF_CNT);
    uint32_t* U     = (uint32_t*)(smem_raw + OFF_U);
    uint32_t* base  = (uint32_t*)(smem_raw + OFF_BASE);
    uint32_t* aux   = (uint32_t*)(smem_raw + OFF_AUX);
    uint32_t* ovfn  = (uint32_t*)(smem_raw + OFF_OVFN);
    float*    s_top = (float*)(smem_raw + OFF_SCAL);   // [7]
    float*    s_bot = s_top + 8;                       // [7]
    float*    s_win = s_top + 16;                      // [7]
    float*    s_los = s_top + 24;                      // [7]

    const int tid  = threadIdx.x;
    const int wid  = tid >> 5;
    const int lane = tid & 31;
    const int row  = blockIdx.x;
    const float*  xr  = x + (size_t)row * I_COLS;
    const float4* xr4 = (const float4*)xr;

    // ---- init: monotone splitter table + zero counters ----
    for (int i = tid; i < NB - 1; i += BT) {
        float pi = (float)(i + 1) * (1.0f / (float)NB);
        float q  = 0.58754f * __logf((1.0f - pi) / pi);
        U[i] = kd(q);
    }
    if (tid == 0) { U[NB - 1] = 0xFFFFFFFFu; base[NB] = I_COLS; ovfn[0] = 0; }
    for (int i = tid; i < NB; i += BT) cnt[i] = 0;
    __syncthreads();

    // ---- Phase 1 (single pass): bucket + 1-atomic slot scatter ----
    #pragma unroll
    for (int q4 = 0; q4 < 4; q4++) {
        int vi = tid + q4 * BT;
        float4 xv = xr4[vi];
        int e = vi * 4;
        float vals[4] = {xv.x, xv.y, xv.z, xv.w};
        #pragma unroll
        for (int c = 0; c < 4; c++) {
            float f = vals[c];
            uint32_t u = kd(f);
            int b = bucket_of(f, u, U);
            uint32_t lo = b ? U[b - 1] : 0u;
            bool narrow = (U[b] - lo) <= (1u << 19);
            uint32_t idx = (uint32_t)(e + c);
            uint32_t payload = narrow ? (((u - lo) << 13) | idx) : idx;
            uint32_t pos = atomicAdd(&cnt[b], 1u);
            if (pos < CAP) slots[b * CAP + pos] = payload;
            else           ovf[atomicAdd(ovfn, 1u)] = ((uint32_t)b << 13) | idx;
        }
    }
    __syncthreads();

    // ---- Phase 2: exclusive scan of true sizes (cnt preserved) ----
    {
        uint32_t c0 = 0, c1 = 0;
        if (tid < NPAIR) { c0 = cnt[2 * tid]; c1 = cnt[2 * tid + 1]; }
        uint32_t tsum = c0 + c1;
        uint32_t inc = tsum;
        #pragma unroll
        for (int o = 1; o < 32; o <<= 1) {
            uint32_t n = __shfl_up_sync(0xFFFFFFFFu, inc, o);
            if (lane >= o) inc += n;
        }
        if (lane == 31) aux[wid] = inc;
        __syncthreads();
        if (wid == 0) {
            uint32_t v  = (lane < NW) ? aux[lane] : 0;
            uint32_t vi = v;
            #pragma unroll
            for (int o = 1; o < 32; o <<= 1) {
                uint32_t n = __shfl_up_sync(0xFFFFFFFFu, vi, o);
                if (lane >= o) vi += n;
            }
            if (lane < NW) aux[lane] = vi - v;       // exclusive warp prefix
        }
        __syncthreads();
        if (tid < NPAIR) {
            uint32_t excl = aux[wid] + (inc - tsum);
            base[2 * tid] = excl;
            base[2 * tid + 1] = excl + c0;
        }
    }
    __syncthreads();

    // ---- b_c zero fill (independent; overlaps with sorts) ----
    float* bc = out + (size_t)row * I_COLS;
    float* si = out + (size_t)B_ROWS * I_COLS + (size_t)row * I_COLS;
    {
        float4 z = make_float4(0.f, 0.f, 0.f, 0.f);
        float4* bc4 = (float4*)bc;
        #pragma unroll
        for (int q4 = 0; q4 < 4; q4++) bc4[tid + q4 * BT] = z;
    }

    // ---- Phase 4: per-warp register sorts (two buckets per warp if small) ----
    const int ovfTotal = (int)ovfn[0];
    for (int pb = wid; pb < NPAIR; pb += NW) {
        int b0 = 2 * pb, b1 = b0 + 1;
        int s0 = (int)cnt[b0], s1 = (int)cnt[b1];
        int g0 = (int)base[b0], g1 = (int)base[b1];
        uint32_t lo0 = b0 ? U[b0 - 1] : 0u;
        uint32_t lo1 = U[b0];
        bool nar0 = (U[b0] - lo0) <= (1u << 19);
        bool nar1 = (U[b1] - lo1) <= (1u << 19);
        if (s0 <= 16 && s1 <= 16 && nar0 && nar1) {
            const int half = lane >> 4, m = lane & 15;
            sort16_u32(slots + (half ? b1 : b0) * CAP, half ? s1 : s0,
                       half ? g1 : g0, half ? lo1 : lo0, m, si, s_top, s_bot);
        } else {
            if (s0 > 0) {
                if (s0 <= CAP) {
                    if (nar0) sort_bucket_u32(slots + b0 * CAP, s0, g0, lo0, lane, si, s_top, s_bot);
                    else      sort_bucket_wide(slots + b0 * CAP, s0, g0, xr, lane, si, s_top, s_bot);
                } else bucket_fallback(slots + b0 * CAP, s0, g0, b0, nar0, ovf, ovfTotal, xr, lane, si, s_top, s_bot);
            }
            if (s1 > 0) {
                if (s1 <= CAP) {
                    if (nar1) sort_bucket_u32(slots + b1 * CAP, s1, g1, lo1, lane, si, s_top, s_bot);
                    else      sort_bucket_wide(slots + b1 * CAP, s1, g1, xr, lane, si, s_top, s_bot);
                } else bucket_fallback(slots + b1 * CAP, s1, g1, b1, nar1, ovf, ovfTotal, xr, lane, si, s_top, s_bot);
            }
        }
    }
    __syncthreads();

    // ---- softmaxes ----
    if (tid == 0) {
        float m = s_top[0];
        #pragma unroll
        for (int i = 1; i < G; i++) m = fmaxf(m, s_top[i]);
        float e[G], s = 0.0f;
        #pragma unroll
        for (int i = 0; i < G; i++) { e[i] = expf(s_top[i] - m); s += e[i]; }
        float inv = 1.0f / s;
        #pragma unroll
        for (int i = 0; i < G; i++) s_win[i] = e[i] * inv;

        float m2 = 1.0f - s_bot[0];
        #pragma unroll
        for (int i = 1; i < G; i++) m2 = fmaxf(m2, 1.0f - s_bot[i]);
        float e2[G], s2 = 0.0f;
        #pragma unroll
        for (int i = 0; i < G; i++) { e2[i] = expf((1.0f - s_bot[i]) - m2); s2 += e2[i]; }
        float inv2 = 1.0f / s2;
        #pragma unroll
        for (int i = 0; i < G; i++) s_los[i] = -e2[i] * inv2;
    }
    __syncthreads();

    if (tid < G)          bc[tid] = s_win[tid];
    else if (tid < 2 * G) bc[I_COLS - G + (tid - G)] = s_los[tid - G];
}

extern "C" void kernel_launch(void* const* d_in, const int* in_sizes, int n_in,
                              void* d_out, int out_size)
{
    (void)in_sizes; (void)n_in; (void)out_size;
    const float* x = (const float*)d_in[0];
    float* out = (float*)d_out;

    cudaFuncSetAttribute(portfolio_slot_kernel,
                         cudaFuncAttributeMaxDynamicSharedMemorySize,
                         (int)SMEM_BYTES);
    portfolio_slot_kernel<<<B_ROWS, BT, SMEM_BYTES>>>(x, out);
}